// round 9
// baseline (speedup 1.0000x reference)
#include <cuda_runtime.h>
#include <cstdint>

#define POOL 14
#define IMG_H 200
#define IMG_W 200
#define IMG_C 1024
#define NUM_ROIS 512

#define NCHUNK 4                       // 256-ch slices -> 41MB image slice, L2-resident
#define CHUNK_FLOATS (IMG_C / NCHUNK)  // 256 floats = 1024 B per cell-chunk
#define LANES_PER_CELL 16              // each lane handles 2x 32B (8 floats) per batch
#define CELLS_PER_BLOCK 16
#define THREADS (LANES_PER_CELL * CELLS_PER_BLOCK)  // 256
#define CELL_BYTES (CHUNK_FLOATS * 4)  // 1024 B

// ---- packed f32x2 helpers (sm_103a) ----
__device__ __forceinline__ unsigned long long pk2(float a, float b) {
    unsigned long long r;
    asm("mov.b64 %0, {%1, %2};" : "=l"(r) : "f"(a), "f"(b));
    return r;
}
__device__ __forceinline__ unsigned long long mul2(unsigned long long a, unsigned long long b) {
    unsigned long long r;
    asm("mul.rn.f32x2 %0, %1, %2;" : "=l"(r) : "l"(a), "l"(b));
    return r;
}
__device__ __forceinline__ unsigned long long fma2(unsigned long long a, unsigned long long b,
                                                   unsigned long long c) {
    unsigned long long r;
    asm("fma.rn.f32x2 %0, %1, %2, %3;" : "=l"(r) : "l"(a), "l"(b), "l"(c));
    return r;
}

// 256-bit image load with L2 evict_last (pins the 41MB slice in L2).
// Returns 4x packed-f32x2 (8 floats = 32B).
__device__ __forceinline__ void ldg256_el(const float* p,
                                          unsigned long long& r0, unsigned long long& r1,
                                          unsigned long long& r2, unsigned long long& r3) {
    asm volatile("ld.global.nc.L2::evict_last.v4.b64 {%0,%1,%2,%3}, [%4];"
                 : "=l"(r0), "=l"(r1), "=l"(r2), "=l"(r3) : "l"(p));
}

__device__ __forceinline__ uint32_t smem_u32(const void* p) {
    uint32_t a;
    asm("{ .reg .u64 t; cvta.to.shared.u64 t, %1; cvt.u32.u64 %0, t; }" : "=r"(a) : "l"(p));
    return a;
}

// grid = (cells/16, NCHUNK). Chunk-outer keeps each 41MB channel slice
// L2-resident (~472MB DRAM traffic). LSU diet: 256-bit loads (8 per thread
// vs 16) + smem-staged 1KB bulk async stores (replaces 12cyc STG.128 path).
__global__ void __launch_bounds__(THREADS)
roi_resize_kernel(const float* __restrict__ img,
                  const int* __restrict__ rois,
                  float* __restrict__ out)
{
    __shared__ float sout[CELLS_PER_BLOCK][CHUNK_FLOATS];  // 16 KB

    const int cell_local = threadIdx.x >> 4;        // 0..15
    const int c          = threadIdx.x & 15;        // lane within cell

    const int idx  = blockIdx.x * CELLS_PER_BLOCK + cell_local;  // 0..100351
    const int roi  = idx / (POOL * POOL);
    const int cell = idx - roi * (POOL * POOL);
    const int py   = cell / POOL;
    const int px   = cell - py * POOL;

    const int chunk_off = blockIdx.y * CHUNK_FLOATS;

    const int4 box = reinterpret_cast<const int4*>(rois)[roi];
    const int bx = box.x, by = box.y, bw = box.z, bh = box.w;

    // Match reference math: fraction from UNclipped floor.
    const float sy = (float)py * ((float)bh / (float)POOL);
    const float sx = (float)px * ((float)bw / (float)POOL);
    const int y0 = (int)floorf(sy);
    const int x0 = (int)floorf(sx);
    const float wy = sy - (float)y0;
    const float wx = sx - (float)x0;

    const int y0c = min(max(y0, 0), bh - 1);
    const int y1c = min(max(y0 + 1, 0), bh - 1);
    const int x0c = min(max(x0, 0), bw - 1);
    const int x1c = min(max(x0 + 1, 0), bw - 1);

    const int iy0 = by + y0c;
    const int iy1 = by + y1c;
    const int ix0 = bx + x0c;
    const int ix1 = bx + x1c;

    const unsigned long long wx2   = pk2(wx, wx);
    const unsigned long long omwx2 = pk2(1.0f - wx, 1.0f - wx);
    const unsigned long long wy2   = pk2(wy, wy);
    const unsigned long long omwy2 = pk2(1.0f - wy, 1.0f - wy);

    const float* base = img + chunk_off;
    const float* __restrict__ p00 = base + ((size_t)iy0 * IMG_W + ix0) * IMG_C;
    const float* __restrict__ p01 = base + ((size_t)iy0 * IMG_W + ix1) * IMG_C;
    const float* __restrict__ p10 = base + ((size_t)iy1 * IMG_W + ix0) * IMG_C;
    const float* __restrict__ p11 = base + ((size_t)iy1 * IMG_W + ix1) * IMG_C;

    // lerp of one packed pair
#define LERP2(g00v, g01v, g10v, g11v)                                        \
    fma2(fma2(g11v, wx2, mul2(g10v, omwx2)), wy2,                            \
         mul2(fma2(g01v, wx2, mul2(g00v, omwx2)), omwy2))

    // 2 batches; each batch: 4 corners x 32B (LDG.256). Lane covers floats
    // [h*128 + c*8, +8) of the 256-float cell-chunk. Fully coalesced:
    // 16 lanes x 32B = 512B contiguous per corner per batch.
#pragma unroll
    for (int h = 0; h < 2; h++) {
        const int foff = h * 128 + c * 8;   // float offset within chunk

        unsigned long long g00a, g00b, g00c, g00d;
        unsigned long long g01a, g01b, g01c, g01d;
        unsigned long long g10a, g10b, g10c, g10d;
        unsigned long long g11a, g11b, g11c, g11d;
        ldg256_el(p00 + foff, g00a, g00b, g00c, g00d);
        ldg256_el(p01 + foff, g01a, g01b, g01c, g01d);
        ldg256_el(p10 + foff, g10a, g10b, g10c, g10d);
        ldg256_el(p11 + foff, g11a, g11b, g11c, g11d);

        const unsigned long long r0 = LERP2(g00a, g01a, g10a, g11a);
        const unsigned long long r1 = LERP2(g00b, g01b, g10b, g11b);
        const unsigned long long r2 = LERP2(g00c, g01c, g10c, g11c);
        const unsigned long long r3 = LERP2(g00d, g01d, g10d, g11d);

        const uint32_t s = smem_u32(&sout[cell_local][foff]);
        asm volatile("st.shared.v2.b64 [%0], {%1, %2};"
                     :: "r"(s), "l"(r0), "l"(r1) : "memory");
        asm volatile("st.shared.v2.b64 [%0+16], {%1, %2};"
                     :: "r"(s), "l"(r2), "l"(r3) : "memory");
    }
#undef LERP2

    __syncthreads();

    // One 1KB bulk async store per cell, evict_first so the output stream
    // doesn't displace the L2-resident image slice.
    if (threadIdx.x < CELLS_PER_BLOCK) {
        asm volatile("fence.proxy.async.shared::cta;" ::: "memory");
        const int my_idx = blockIdx.x * CELLS_PER_BLOCK + threadIdx.x;
        float* dst = out + (size_t)my_idx * IMG_C + chunk_off;
        const uint32_t src = smem_u32(&sout[threadIdx.x][0]);
        unsigned long long pol;
        asm volatile("createpolicy.fractional.L2::evict_first.b64 %0, 1.0;" : "=l"(pol));
        asm volatile("cp.async.bulk.global.shared::cta.bulk_group.L2::cache_hint "
                     "[%0], [%1], %2, %3;"
                     :: "l"(dst), "r"(src), "r"((uint32_t)CELL_BYTES), "l"(pol) : "memory");
        asm volatile("cp.async.bulk.commit_group;" ::: "memory");
        // Drain before CTA exit (smem source lifetime).
        asm volatile("cp.async.bulk.wait_group 0;" ::: "memory");
    }
}

extern "C" void kernel_launch(void* const* d_in, const int* in_sizes, int n_in,
                              void* d_out, int out_size)
{
    const float* img  = (const float*)d_in[0];
    const int*   rois = (const int*)d_in[1];
    if (in_sizes[0] == NUM_ROIS * 4) {  // defensive: swapped order
        rois = (const int*)d_in[0];
        img  = (const float*)d_in[1];
    }
    float* out = (float*)d_out;

    dim3 grid((NUM_ROIS * POOL * POOL) / CELLS_PER_BLOCK, NCHUNK);  // (6272, 4)
    roi_resize_kernel<<<grid, THREADS>>>(img, rois, out);
}

// round 10
// speedup vs baseline: 1.1235x; 1.1235x over previous
#include <cuda_runtime.h>
#include <cstdint>

#define POOL 14
#define IMG_H 200
#define IMG_W 200
#define IMG_C 1024
#define NUM_ROIS 512

#define NCHUNK 4                       // 256-ch slices -> 41MB image slice, L2-resident
#define CHUNK_FLOATS (IMG_C / NCHUNK)  // 256 floats = 1KB per cell-chunk
#define LANES_PER_CELL 8               // each lane: 4 segments of 32B (8 floats)
#define CELLS_PER_BLOCK 32
#define THREADS (LANES_PER_CELL * CELLS_PER_BLOCK)  // 256

// ---- packed f32x2 helpers (sm_103a) ----
__device__ __forceinline__ unsigned long long pk2(float a, float b) {
    unsigned long long r;
    asm("mov.b64 %0, {%1, %2};" : "=l"(r) : "f"(a), "f"(b));
    return r;
}
__device__ __forceinline__ unsigned long long mul2(unsigned long long a, unsigned long long b) {
    unsigned long long r;
    asm("mul.rn.f32x2 %0, %1, %2;" : "=l"(r) : "l"(a), "l"(b));
    return r;
}
__device__ __forceinline__ unsigned long long fma2(unsigned long long a, unsigned long long b,
                                                   unsigned long long c) {
    unsigned long long r;
    asm("fma.rn.f32x2 %0, %1, %2, %3;" : "=l"(r) : "l"(a), "l"(b), "l"(c));
    return r;
}

// 256-bit global load (sm_100+): returns 4x packed f32x2 = 8 floats = 32B.
__device__ __forceinline__ void ldg256(const float* p,
                                       unsigned long long& r0, unsigned long long& r1,
                                       unsigned long long& r2, unsigned long long& r3) {
    asm volatile("ld.global.nc.v4.b64 {%0,%1,%2,%3}, [%4];"
                 : "=l"(r0), "=l"(r1), "=l"(r2), "=l"(r3) : "l"(p));
}

// 256-bit streaming store (evict-first-ish .cs): 8 floats = 32B.
__device__ __forceinline__ void stg256_cs(float* p,
                                          unsigned long long r0, unsigned long long r1,
                                          unsigned long long r2, unsigned long long r3) {
    asm volatile("st.global.cs.v4.b64 [%0], {%1,%2,%3,%4};"
                 :: "l"(p), "l"(r0), "l"(r1), "l"(r2), "l"(r3) : "memory");
}

// grid = (cells/32, NCHUNK). Chunk-outer keeps each 41MB channel slice
// L2-resident across all ROIs (~472MB DRAM traffic, measured R5/R7/R9).
// LSU diet vs R5: 256-bit loads AND stores halve warp-op counts
// (LDG 3.2M->1.6M, STG 803K->401K) with zero smem/sync overhead.
__global__ void __launch_bounds__(THREADS)
roi_resize_kernel(const float* __restrict__ img,
                  const int* __restrict__ rois,
                  float* __restrict__ out)
{
    const int cell_local = threadIdx.x >> 3;        // 0..31
    const int c          = threadIdx.x & 7;         // lane within cell

    const int idx  = blockIdx.x * CELLS_PER_BLOCK + cell_local;  // 0..100351
    const int roi  = idx / (POOL * POOL);
    const int cell = idx - roi * (POOL * POOL);
    const int py   = cell / POOL;
    const int px   = cell - py * POOL;

    const int chunk_off = blockIdx.y * CHUNK_FLOATS;

    const int4 box = reinterpret_cast<const int4*>(rois)[roi];
    const int bx = box.x, by = box.y, bw = box.z, bh = box.w;

    // Match reference math: fraction from UNclipped floor.
    const float sy = (float)py * ((float)bh / (float)POOL);
    const float sx = (float)px * ((float)bw / (float)POOL);
    const int y0 = (int)floorf(sy);
    const int x0 = (int)floorf(sx);
    const float wy = sy - (float)y0;
    const float wx = sx - (float)x0;

    const int y0c = min(max(y0, 0), bh - 1);
    const int y1c = min(max(y0 + 1, 0), bh - 1);
    const int x0c = min(max(x0, 0), bw - 1);
    const int x1c = min(max(x0 + 1, 0), bw - 1);

    const int iy0 = by + y0c;
    const int iy1 = by + y1c;
    const int ix0 = bx + x0c;
    const int ix1 = bx + x1c;

    const unsigned long long wx2   = pk2(wx, wx);
    const unsigned long long omwx2 = pk2(1.0f - wx, 1.0f - wx);
    const unsigned long long wy2   = pk2(wy, wy);
    const unsigned long long omwy2 = pk2(1.0f - wy, 1.0f - wy);

    const float* base = img + chunk_off;
    const float* __restrict__ p00 = base + ((size_t)iy0 * IMG_W + ix0) * IMG_C;
    const float* __restrict__ p01 = base + ((size_t)iy0 * IMG_W + ix1) * IMG_C;
    const float* __restrict__ p10 = base + ((size_t)iy1 * IMG_W + ix0) * IMG_C;
    const float* __restrict__ p11 = base + ((size_t)iy1 * IMG_W + ix1) * IMG_C;

    float* __restrict__ o = out + (size_t)idx * IMG_C + chunk_off;

    // lerp of one packed pair
#define LERP2(g00v, g01v, g10v, g11v)                                        \
    fma2(fma2(g11v, wx2, mul2(g10v, omwx2)), wy2,                            \
         mul2(fma2(g01v, wx2, mul2(g00v, omwx2)), omwy2))

    // 4 segments; each: 4 corners x 32B LDG.256 (8 lanes x 32B = 256B
    // contiguous per corner -> fully coalesced), lerp, 1 STG.256.
#pragma unroll
    for (int s = 0; s < 4; s++) {
        const int foff = s * 64 + c * 8;   // float offset within 256-float chunk

        unsigned long long g00a, g00b, g00c, g00d;
        unsigned long long g01a, g01b, g01c, g01d;
        unsigned long long g10a, g10b, g10c, g10d;
        unsigned long long g11a, g11b, g11c, g11d;
        ldg256(p00 + foff, g00a, g00b, g00c, g00d);
        ldg256(p01 + foff, g01a, g01b, g01c, g01d);
        ldg256(p10 + foff, g10a, g10b, g10c, g10d);
        ldg256(p11 + foff, g11a, g11b, g11c, g11d);

        const unsigned long long r0 = LERP2(g00a, g01a, g10a, g11a);
        const unsigned long long r1 = LERP2(g00b, g01b, g10b, g11b);
        const unsigned long long r2 = LERP2(g00c, g01c, g10c, g11c);
        const unsigned long long r3 = LERP2(g00d, g01d, g10d, g11d);

        stg256_cs(o + foff, r0, r1, r2, r3);
    }
#undef LERP2
}

extern "C" void kernel_launch(void* const* d_in, const int* in_sizes, int n_in,
                              void* d_out, int out_size)
{
    const float* img  = (const float*)d_in[0];
    const int*   rois = (const int*)d_in[1];
    if (in_sizes[0] == NUM_ROIS * 4) {  // defensive: swapped order
        rois = (const int*)d_in[0];
        img  = (const float*)d_in[1];
    }
    float* out = (float*)d_out;

    dim3 grid((NUM_ROIS * POOL * POOL) / CELLS_PER_BLOCK, NCHUNK);  // (3136, 4)
    roi_resize_kernel<<<grid, THREADS>>>(img, rois, out);
}